// round 12
// baseline (speedup 1.0000x reference)
#include <cuda_runtime.h>
#include <cstdint>

// ---------------------------------------------------------------------------
// B=32768, N=17 joints, D=2, K=3, H=64 (k/w MLPs), 2H=128 (b MLP)
// Outputs (flattened float32): out (B,N,K,5) | k_js (B,N) | mask (B,N,K)
// ---------------------------------------------------------------------------
#define NB        32768
#define NJ        17
#define TILE_B    32
#define NTILES    (NB / TILE_B)          // 1024
#define NQUADS    (NTILES / 4)           // 256
#define NBJ       64                     // blocks per joint (64*4 warps = 256 quads)
#define NWARPS    4                      // warps per block

#define JSTRIDE   3092                   // floats per joint (16B-aligned stride)
#define WFLOATS   (NJ * JSTRIDE)

// packed per-joint layout (floats):
//  [0,384):     kMLP rows, 32 rows x 12: [W1d0 pair, W1d1 pair | W2o0, W2o1 | W2o2, b1]
//  [384,768):   wMLP rows, same
//  [768,3072):  bMLP rows, 64 row-pairs x 36 floats:
//     G0=[w0a,w0a,w1a,w1a] G1=[ba,ba,w0b,w0b] G2=[w1b,w1b,bb,bb]
//     G3-G5 = W2 row a (12 floats, output pairs)  G6-G8 = W2 row b
//  [3072,3075): kb2  [3075,3078): wb2  [3078,3090): bb2  [3090,3092): pad
#define SEC_W     384
#define SEC_B     768
#define OFF_KB2   3072
#define OFF_WB2   3075
#define OFF_BB2   3078

#define KJS_OFF     8355840ull           // B*N*K*5
#define MASK_OFF    8912896ull

typedef unsigned long long ull;

static __device__ __forceinline__ ull pk2(float lo, float hi) {
    ull r; asm("mov.b64 %0,{%1,%2};" : "=l"(r) : "f"(lo), "f"(hi)); return r;
}
static __device__ __forceinline__ ull fma2(ull a, ull b, ull c) {
    ull d; asm("fma.rn.f32x2 %0,%1,%2,%3;" : "=l"(d) : "l"(a), "l"(b), "l"(c)); return d;
}
static __device__ __forceinline__ ull relu2(ull g) {
    float lo, hi; asm("mov.b64 {%0,%1},%2;" : "=f"(lo), "=f"(hi) : "l"(g));
    lo = fmaxf(lo, 0.f); hi = fmaxf(hi, 0.f);
    ull r; asm("mov.b64 %0,{%1,%2};" : "=l"(r) : "f"(lo), "f"(hi)); return r;
}
static __device__ __forceinline__ float rsum2(ull a) {
    float lo, hi; asm("mov.b64 {%0,%1},%2;" : "=f"(lo), "=f"(hi) : "l"(a));
    return lo + hi;
}
static __device__ __forceinline__ float2 up2(ull a) {
    float lo, hi; asm("mov.b64 {%0,%1},%2;" : "=f"(lo), "=f"(hi) : "l"(a));
    return make_float2(lo, hi);
}

__device__ __align__(16) float g_packed[WFLOATS];

// ---------------------------------------------------------------------------
// Setup kernel: pack weights (17 blocks x 128 threads).
// ---------------------------------------------------------------------------
__global__ void pack_weights(
    const float* __restrict__ kW1, const float* __restrict__ kb1,
    const float* __restrict__ kW2, const float* __restrict__ kb2,
    const float* __restrict__ wW1, const float* __restrict__ wb1,
    const float* __restrict__ wW2, const float* __restrict__ wb2,
    const float* __restrict__ bW1, const float* __restrict__ bb1,
    const float* __restrict__ bW2, const float* __restrict__ bb2)
{
    const int n = blockIdx.x;
    const int t = threadIdx.x;
    float* dst = g_packed + n * JSTRIDE;

    if (t < 32) {                       // kMLP row jp = t
        const int jp = t, j = 2 * jp;
        float* r = dst + jp * 12;
        r[0] = kW1[n * 128 + j];          r[1] = kW1[n * 128 + j + 1];
        r[2] = kW1[n * 128 + 64 + j];     r[3] = kW1[n * 128 + 64 + j + 1];
        #pragma unroll
        for (int o = 0; o < 3; o++) {
            r[4 + 2 * o] = kW2[n * 192 + j * 3 + o];
            r[5 + 2 * o] = kW2[n * 192 + (j + 1) * 3 + o];
        }
        r[10] = kb1[n * 64 + j];          r[11] = kb1[n * 64 + j + 1];
    } else if (t < 64) {                // wMLP row jp = t-32
        const int jp = t - 32, j = 2 * jp;
        float* r = dst + SEC_W + jp * 12;
        r[0] = wW1[n * 128 + j];          r[1] = wW1[n * 128 + j + 1];
        r[2] = wW1[n * 128 + 64 + j];     r[3] = wW1[n * 128 + 64 + j + 1];
        #pragma unroll
        for (int o = 0; o < 3; o++) {
            r[4 + 2 * o] = wW2[n * 192 + j * 3 + o];
            r[5 + 2 * o] = wW2[n * 192 + (j + 1) * 3 + o];
        }
        r[10] = wb1[n * 64 + j];          r[11] = wb1[n * 64 + j + 1];
    } else {                            // bMLP row-pair jp = t-64, units a=2jp, b=2jp+1
        const int jp = t - 64, a = 2 * jp, b = a + 1;
        float* r = dst + SEC_B + jp * 36;
        const float w0a = bW1[n * 256 + a],       w1a = bW1[n * 256 + 128 + a];
        const float w0b = bW1[n * 256 + b],       w1b = bW1[n * 256 + 128 + b];
        const float ba  = bb1[n * 128 + a],       bbv = bb1[n * 128 + b];
        r[0] = w0a; r[1] = w0a; r[2]  = w1a; r[3]  = w1a;   // G0
        r[4] = ba;  r[5] = ba;  r[6]  = w0b; r[7]  = w0b;   // G1
        r[8] = w1b; r[9] = w1b; r[10] = bbv; r[11] = bbv;   // G2
        #pragma unroll
        for (int o = 0; o < 12; o++) {                      // G3-G5: W2 row a
            r[12 + o] = bW2[n * 1536 + a * 12 + o];
            r[24 + o] = bW2[n * 1536 + b * 12 + o];         // G6-G8: W2 row b
        }
    }
    if (t == 0) {
        #pragma unroll
        for (int o = 0; o < 3; o++)  { dst[OFF_KB2 + o] = kb2[n * 3 + o];
                                       dst[OFF_WB2 + o] = wb2[n * 3 + o]; }
        #pragma unroll
        for (int o = 0; o < 12; o++)   dst[OFF_BB2 + o] = bb2[n * 12 + o];
        dst[3090] = 0.f; dst[3091] = 0.f;
    }
}

// Per-point epilogue: argmax, softmax, exp(sigma), stable descending sort.
static __device__ __forceinline__ void finish(const float kl[3], const float wl[3],
                                              const float pv[12],
                                              float v[15], int& am)
{
    am = 0; float bm = kl[0];
    if (kl[1] > bm) { bm = kl[1]; am = 1; }
    if (kl[2] > bm) { bm = kl[2]; am = 2; }

    float m  = fmaxf(wl[0], fmaxf(wl[1], wl[2]));
    float e0 = expf(wl[0] - m), e1 = expf(wl[1] - m), e2 = expf(wl[2] - m);
    float inv = 1.0f / (e0 + e1 + e2);
    float wv[3] = { e0 * inv, e1 * inv, e2 * inv };

    float4 pl[3]; float ws[3];
    #pragma unroll
    for (int k = 0; k < 3; k++) {
        pl[k] = make_float4(pv[4 * k], pv[4 * k + 1],
                            expf(pv[4 * k + 2]), expf(pv[4 * k + 3]));
        ws[k] = wv[k];
    }
    // stable descending sort by w (strict >): matches stable jnp.argsort(-w)
    #define CSWAP(i_, j_)                                               \
        if (ws[j_] > ws[i_]) {                                          \
            float tw = ws[i_]; ws[i_] = ws[j_]; ws[j_] = tw;            \
            float4 tp = pl[i_]; pl[i_] = pl[j_]; pl[j_] = tp;           \
        }
    CSWAP(0, 1) CSWAP(1, 2) CSWAP(0, 1)
    #undef CSWAP

    #pragma unroll
    for (int k = 0; k < 3; k++) {
        v[5 * k + 0] = wv[k];
        v[5 * k + 1] = pl[k].x;
        v[5 * k + 2] = pl[k].y;
        v[5 * k + 3] = pl[k].z;
        v[5 * k + 4] = pl[k].w;
    }
}

// Stage one point's 15 outputs + kjs/mask, then coalesced flush of one tile.
static __device__ __forceinline__ void stage_and_flush(
    float* __restrict__ myStage, float* __restrict__ out,
    const float v[15], int am, int tile, int joint, int lane)
{
    const int j15 = lane & 15;
    const int hi  = lane >> 4;
    float* op = myStage + lane * 17;
    #pragma unroll
    for (int k = 0; k < 15; k++) op[k] = v[k];

    const int b = tile * TILE_B + lane;
    const size_t pidx = (size_t)b * NJ + joint;
    out[KJS_OFF + pidx] = (float)(am + 1);
    float* gm = out + MASK_OFF + pidx * 3;
    gm[0] = 1.0f;
    gm[1] = (am >= 1) ? 1.0f : 0.0f;
    gm[2] = (am >= 2) ? 1.0f : 0.0f;
    __syncwarp();

    const size_t base = (size_t)tile * (TILE_B * NJ * 15) + (size_t)joint * 15;
    #pragma unroll
    for (int q = 0; q < 16; q++) {
        const int c = 2 * q + hi;
        if (j15 < 15)
            out[base + (size_t)c * (NJ * 15) + j15] = myStage[c * 17 + j15];
    }
    __syncwarp();
}

// ---------------------------------------------------------------------------
// Main kernel: 128 threads (4 warps), 4 blocks/SM (128-reg cap, NO spills).
// Each warp handles ONE quad of tiles (4 points/thread): every weight LDS
// amortized over 4 points -> ~6 LDS/pt vs 11 in the pair version.
// bMLP uses OUTPUT-packed f32x2 accumulation (6 ull/pt) with pre-duplicated
// W1 weights so h is splat-free; unsplit K loop (no W1 reload, no stash).
// ---------------------------------------------------------------------------
__global__ void __launch_bounds__(128, 4)
mlp_main(const float* __restrict__ pred, float* __restrict__ out)
{
    __shared__ float swt[JSTRIDE];                 // 12368 B packed weights
    __shared__ float sStage[NWARPS][32 * 17];      // 8704 B staging, pad 17
    __shared__ float sKW[NWARPS][32 * 25];         // 12800 B kl/wl stash, pad 25

    const int joint = blockIdx.x % NJ;
    const int blk   = blockIdx.x / NJ;             // 0..NBJ-1
    const int wid   = threadIdx.x >> 5;
    const int lane  = threadIdx.x & 31;

    {   // stage this joint's weights into smem (coalesced float4)
        const float4* src = (const float4*)(g_packed + joint * JSTRIDE);
        float4* dst = (float4*)swt;
        #pragma unroll
        for (int i = threadIdx.x; i < JSTRIDE / 4; i += 128) dst[i] = src[i];
    }
    __syncthreads();

    float* myStage = sStage[wid];
    float* st = sKW[wid] + lane * 25;   // [0:12) kl x4 pts, [12:24) wl x4 pts

    const int qr = blk * NWARPS + wid;  // 0..255, exact cover of all quads
    const int t0 = 4 * qr;

    // ---- load 4 points ----
    ull X0[4], X1[4];
    #pragma unroll
    for (int p = 0; p < 4; p++) {
        const int b = (t0 + p) * TILE_B + lane;
        const float2 x = *(const float2*)(pred + ((size_t)b * NJ + joint) * 2);
        X0[p] = pk2(x.x, x.x);
        X1[p] = pk2(x.y, x.y);
    }

    // ---- kMLP (2->64->3), quad, packed-hidden ----
    {
        ull a[4][3];
        #pragma unroll
        for (int p = 0; p < 4; p++) { a[p][0] = 0; a[p][1] = 0; a[p][2] = 0; }
        #pragma unroll 4
        for (int jp = 0; jp < 32; jp++) {
            const float* r = swt + jp * 12;
            ulonglong2 q0 = *(const ulonglong2*)(r);
            ulonglong2 q1 = *(const ulonglong2*)(r + 4);
            ulonglong2 q2 = *(const ulonglong2*)(r + 8);
            #pragma unroll
            for (int p = 0; p < 4; p++) {
                ull h = relu2(fma2(X0[p], q0.x, fma2(X1[p], q0.y, q2.y)));
                a[p][0] = fma2(h, q1.x, a[p][0]);
                a[p][1] = fma2(h, q1.y, a[p][1]);
                a[p][2] = fma2(h, q2.x, a[p][2]);
            }
        }
        const float b0 = swt[OFF_KB2], b1 = swt[OFF_KB2 + 1], b2 = swt[OFF_KB2 + 2];
        #pragma unroll
        for (int p = 0; p < 4; p++) {
            st[p * 3 + 0] = rsum2(a[p][0]) + b0;
            st[p * 3 + 1] = rsum2(a[p][1]) + b1;
            st[p * 3 + 2] = rsum2(a[p][2]) + b2;
        }
    }

    // ---- wMLP (2->64->3), quad ----
    {
        ull a[4][3];
        #pragma unroll
        for (int p = 0; p < 4; p++) { a[p][0] = 0; a[p][1] = 0; a[p][2] = 0; }
        #pragma unroll 4
        for (int jp = 0; jp < 32; jp++) {
            const float* r = swt + SEC_W + jp * 12;
            ulonglong2 q0 = *(const ulonglong2*)(r);
            ulonglong2 q1 = *(const ulonglong2*)(r + 4);
            ulonglong2 q2 = *(const ulonglong2*)(r + 8);
            #pragma unroll
            for (int p = 0; p < 4; p++) {
                ull h = relu2(fma2(X0[p], q0.x, fma2(X1[p], q0.y, q2.y)));
                a[p][0] = fma2(h, q1.x, a[p][0]);
                a[p][1] = fma2(h, q1.y, a[p][1]);
                a[p][2] = fma2(h, q2.x, a[p][2]);
            }
        }
        const float b0 = swt[OFF_WB2], b1 = swt[OFF_WB2 + 1], b2 = swt[OFF_WB2 + 2];
        #pragma unroll
        for (int p = 0; p < 4; p++) {
            st[12 + p * 3 + 0] = rsum2(a[p][0]) + b0;
            st[12 + p * 3 + 1] = rsum2(a[p][1]) + b1;
            st[12 + p * 3 + 2] = rsum2(a[p][2]) + b2;
        }
    }

    // ---- bMLP (2->128->12), quad, OUTPUT-packed acc (6 ull/pt = 48 regs) ----
    ull acc[4][6];
    #pragma unroll
    for (int p = 0; p < 4; p++)
        #pragma unroll
        for (int o = 0; o < 6; o++) acc[p][o] = 0;

    #pragma unroll 1
    for (int jp = 0; jp < 64; jp++) {
        const float* r = swt + SEC_B + jp * 36;
        ulonglong2 g0 = *(const ulonglong2*)(r);        // (w0a,w0a),(w1a,w1a)
        ulonglong2 g1 = *(const ulonglong2*)(r + 4);    // (ba,ba),(w0b,w0b)
        ulonglong2 g2 = *(const ulonglong2*)(r + 8);    // (w1b,w1b),(bb,bb)
        ulonglong2 a0 = *(const ulonglong2*)(r + 12);   // W2a pairs 01,23
        ulonglong2 a1 = *(const ulonglong2*)(r + 16);   //           45,67
        ulonglong2 a2 = *(const ulonglong2*)(r + 20);   //           89,AB
        ulonglong2 b0 = *(const ulonglong2*)(r + 24);   // W2b pairs 01,23
        ulonglong2 b1 = *(const ulonglong2*)(r + 28);   //           45,67
        ulonglong2 b2 = *(const ulonglong2*)(r + 32);   //           89,AB
        #pragma unroll
        for (int p = 0; p < 4; p++) {
            ull ha = relu2(fma2(X0[p], g0.x, fma2(X1[p], g0.y, g1.x)));  // (ha,ha)
            acc[p][0] = fma2(ha, a0.x, acc[p][0]);
            acc[p][1] = fma2(ha, a0.y, acc[p][1]);
            acc[p][2] = fma2(ha, a1.x, acc[p][2]);
            acc[p][3] = fma2(ha, a1.y, acc[p][3]);
            acc[p][4] = fma2(ha, a2.x, acc[p][4]);
            acc[p][5] = fma2(ha, a2.y, acc[p][5]);
            ull hb = relu2(fma2(X0[p], g1.y, fma2(X1[p], g2.x, g2.y)));  // (hb,hb)
            acc[p][0] = fma2(hb, b0.x, acc[p][0]);
            acc[p][1] = fma2(hb, b0.y, acc[p][1]);
            acc[p][2] = fma2(hb, b1.x, acc[p][2]);
            acc[p][3] = fma2(hb, b1.y, acc[p][3]);
            acc[p][4] = fma2(hb, b2.x, acc[p][4]);
            acc[p][5] = fma2(hb, b2.y, acc[p][5]);
        }
    }

    // ---- epilogue + flush per tile ----
    #pragma unroll
    for (int p = 0; p < 4; p++) {
        float kl[3] = { st[p * 3], st[p * 3 + 1], st[p * 3 + 2] };
        float wl[3] = { st[12 + p * 3], st[12 + p * 3 + 1], st[12 + p * 3 + 2] };
        float pv[12];
        #pragma unroll
        for (int o = 0; o < 6; o++) {
            float2 ab = up2(acc[p][o]);
            pv[2 * o + 0] = ab.x + swt[OFF_BB2 + 2 * o + 0];
            pv[2 * o + 1] = ab.y + swt[OFF_BB2 + 2 * o + 1];
        }

        float v[15]; int am;
        finish(kl, wl, pv, v, am);
        stage_and_flush(myStage, out, v, am, t0 + p, joint, lane);
    }
}

// ---------------------------------------------------------------------------
extern "C" void kernel_launch(void* const* d_in, const int* in_sizes, int n_in,
                              void* d_out, int out_size)
{
    const float* pred = (const float*)d_in[0];
    const float* kW1 = (const float*)d_in[1];
    const float* kb1 = (const float*)d_in[2];
    const float* kW2 = (const float*)d_in[3];
    const float* kb2 = (const float*)d_in[4];
    const float* wW1 = (const float*)d_in[5];
    const float* wb1 = (const float*)d_in[6];
    const float* wW2 = (const float*)d_in[7];
    const float* wb2 = (const float*)d_in[8];
    const float* bW1 = (const float*)d_in[9];
    const float* bb1 = (const float*)d_in[10];
    const float* bW2 = (const float*)d_in[11];
    const float* bb2 = (const float*)d_in[12];
    float* out = (float*)d_out;

    pack_weights<<<NJ, 128>>>(kW1, kb1, kW2, kb2,
                              wW1, wb1, wW2, wb2,
                              bW1, bb1, bW2, bb2);

    mlp_main<<<NJ * NBJ, 128>>>(pred, out);
}